// round 8
// baseline (speedup 1.0000x reference)
#include <cuda_runtime.h>
#include <math.h>
#include <stdint.h>

#define Bq 128
#define Uq 256
#define NG 1280

// ---------------- scratch (static device globals) ----------------------------
__device__ float g_gsum[Bq * NG];
__device__ float g_c  [Bq * Uq];
__device__ float g_fre[Bq * Uq];
__device__ float g_ste[Bq * Uq];
__device__ float g_cos[Bq * Uq];
__device__ float g_sin[Bq * Uq];
__device__ float g_A  [(size_t)Uq * Bq * Uq];   // [k][b][u] fp32 (tf32-rounded), 33.5MB
__device__ float g_xr [Bq * Uq];                // tf32-rounded x
__device__ float g_zr [Bq * Uq];                // tf32-rounded z_prev

__device__ __forceinline__ float hsig(float v) {
    return fminf(fmaxf(0.2f * v + 0.5f, 0.0f), 1.0f);
}
__device__ __forceinline__ float tf32r(float f) {
    uint32_t u;
    asm("cvt.rna.tf32.f32 %0, %1;" : "=r"(u) : "f"(f));
    return __uint_as_float(u);
}

// ---------------- PTX helpers --------------------------------------------------
__device__ __forceinline__ uint32_t smem_u32(const void* p) {
    uint32_t a;
    asm("{ .reg .u64 t; cvta.to.shared.u64 t, %1; cvt.u32.u64 %0, t; }" : "=r"(a) : "l"(p));
    return a;
}
__device__ __forceinline__ void cpa16(uint32_t dst, const void* src) {
    asm volatile("cp.async.cg.shared.global [%0], [%1], 16;" :: "r"(dst), "l"(src) : "memory");
}
__device__ __forceinline__ void cpa_commit() {
    asm volatile("cp.async.commit_group;" ::: "memory");
}
__device__ __forceinline__ void cpa_wait1() {
    asm volatile("cp.async.wait_group 1;" ::: "memory");
}
__device__ __forceinline__ void cpa_wait0() {
    asm volatile("cp.async.wait_group 0;" ::: "memory");
}
__device__ __forceinline__ float lds32(uint32_t a) {
    float v;
    asm volatile("ld.shared.f32 %0, [%1];" : "=f"(v) : "r"(a));
    return v;
}
__device__ __forceinline__ uint32_t lds_rna(uint32_t a) {
    uint32_t u;
    float v = lds32(a);
    asm("cvt.rna.tf32.f32 %0, %1;" : "=r"(u) : "f"(v));
    return u;
}
__device__ __forceinline__ void mma_tf32(float* c, const uint32_t* a, uint32_t b0, uint32_t b1) {
    asm volatile(
        "mma.sync.aligned.m16n8k8.row.col.f32.tf32.tf32.f32 "
        "{%0,%1,%2,%3}, {%4,%5,%6,%7}, {%8,%9}, {%0,%1,%2,%3};"
        : "+f"(c[0]), "+f"(c[1]), "+f"(c[2]), "+f"(c[3])
        : "r"(a[0]), "r"(a[1]), "r"(a[2]), "r"(a[3]), "r"(b0), "r"(b1));
}

// ============================================================================
// Kernel 1: g_gsum = x @ kernel + z_prev @ recur_k + bias.  32x64 tiles.
// Grid (20 j, 4 b), 256 threads, 2x4 per-thread tile.
// ============================================================================
__global__ __launch_bounds__(256) void k_gates_gemm(
    const float* __restrict__ x, const float* __restrict__ z_prev,
    const float* __restrict__ kern, const float* __restrict__ recur,
    const float* __restrict__ bias)
{
    __shared__ float sX[32][33];   // [ku][b], transposed
    __shared__ float sW[32][68];
    const int tid = threadIdx.x;
    const int j0 = blockIdx.x * 64, b0 = blockIdx.y * 32;
    const int rg = tid >> 4, cg = tid & 15;
    float acc[2][4];
#pragma unroll
    for (int i = 0; i < 2; i++)
#pragma unroll
        for (int j = 0; j < 4; j++) acc[i][j] = 0.f;

#pragma unroll
    for (int pass = 0; pass < 2; pass++) {
        const float* L = pass ? z_prev : x;
        const float* W = pass ? recur : kern;
        for (int d0 = 0; d0 < 256; d0 += 32) {
            {
                const int lb = tid >> 3, lu = (tid & 7) * 4;
                float4 v = *(const float4*)&L[(b0 + lb) * 256 + d0 + lu];
                sX[lu][lb] = v.x; sX[lu + 1][lb] = v.y;
                sX[lu + 2][lb] = v.z; sX[lu + 3][lb] = v.w;
            }
#pragma unroll
            for (int i2 = 0; i2 < 2; i2++) {
                const int wu = (tid >> 4) + i2 * 16, wc = (tid & 15) * 4;
                *(float4*)&sW[wu][wc] = *(const float4*)&W[(d0 + wu) * NG + j0 + wc];
            }
            __syncthreads();
#pragma unroll
            for (int kk = 0; kk < 32; kk++) {
                float a0 = sX[kk][rg * 2], a1 = sX[kk][rg * 2 + 1];
                float bb[4];
#pragma unroll
                for (int j = 0; j < 4; j++) bb[j] = sW[kk][cg * 4 + j];
#pragma unroll
                for (int j = 0; j < 4; j++) { acc[0][j] += a0 * bb[j]; acc[1][j] += a1 * bb[j]; }
            }
            __syncthreads();
        }
    }
#pragma unroll
    for (int i = 0; i < 2; i++) {
        const int b = b0 + rg * 2 + i;
#pragma unroll
        for (int j = 0; j < 4; j++) {
            const int jj = j0 + cg * 4 + j;
            g_gsum[b * NG + jj] = acc[i][j] + bias[jj];
        }
    }
}

// ============================================================================
// Kernel 2: elementwise gates + omega out + cos/sin + tf32-rounded x, z_prev
// ============================================================================
__global__ __launch_bounds__(256) void k_gates_ew(
    const float* __restrict__ x, const float* __restrict__ z_prev,
    const float* __restrict__ omg_prev, const float* __restrict__ t,
    float* __restrict__ out_omg)
{
    const int idx = blockIdx.x * blockDim.x + threadIdx.x;
    const int b = idx >> 8, u = idx & 255;
    const float* g = &g_gsum[b * NG];
    const float i_g = hsig(g[u]);
    const float fre = hsig(g[Uq + u]);
    const float ste = hsig(g[2 * Uq + u]);
    const float gg  = tanhf(g[3 * Uq + u]);
    g_c[idx] = i_g * gg; g_fre[idx] = fre; g_ste[idx] = ste;
    const float th = omg_prev[idx] * t[b];
    g_cos[idx] = cosf(th); g_sin[idx] = sinf(th);
    out_omg[idx] = g[4 * Uq + u];
    g_xr[idx] = tf32r(x[idx]);
    g_zr[idx] = tf32r(z_prev[idx]);
}

// ============================================================================
// Kernel 3: Re/Im update + A = sqrt(Re^2+Im^2) -> g_A [k][b][u] (tf32-rounded)
// float4 I/O. Block: one b, 64(i=u) x 64(j=k) tile.
// ============================================================================
__global__ __launch_bounds__(256) void k_reim(
    const float* __restrict__ Re_prev, const float* __restrict__ Im_prev,
    float* __restrict__ Im_out, float* __restrict__ Re_out)
{
    __shared__ float sA[64][65];
    const int b = blockIdx.z, i0 = blockIdx.y * 64, j0 = blockIdx.x * 64;
    const int t16 = threadIdx.x & 15, tr = threadIdx.x >> 4;
    const int j4 = t16 * 4;

    const float4 fre4 = *(const float4*)&g_fre[b * Uq + j0 + j4];
    const float4 cos4 = *(const float4*)&g_cos[b * Uq + j0 + j4];
    const float4 sin4 = *(const float4*)&g_sin[b * Uq + j0 + j4];
    const float frev[4] = {fre4.x, fre4.y, fre4.z, fre4.w};
    const float cosv[4] = {cos4.x, cos4.y, cos4.z, cos4.w};
    const float sinv[4] = {sin4.x, sin4.y, sin4.z, sin4.w};

#pragma unroll
    for (int r = 0; r < 4; r++) {
        const int i = tr + r * 16;
        const float ste_i = g_ste[b * Uq + i0 + i];
        const float ci    = g_c  [b * Uq + i0 + i];
        const size_t idx = ((size_t)b * Uq + (i0 + i)) * Uq + j0 + j4;
        const float4 rp = *(const float4*)&Re_prev[idx];
        const float4 ip = *(const float4*)&Im_prev[idx];
        const float rpv[4] = {rp.x, rp.y, rp.z, rp.w};
        const float ipv[4] = {ip.x, ip.y, ip.z, ip.w};
        float rev[4], imv[4];
#pragma unroll
        for (int q = 0; q < 4; q++) {
            const float f = ste_i * frev[q];
            rev[q] = f * rpv[q] + ci * cosv[q];
            imv[q] = f * ipv[q] + ci * sinv[q];
            sA[i][j4 + q] = tf32r(sqrtf(rev[q] * rev[q] + imv[q] * imv[q]));
        }
        *(float4*)&Re_out[idx] = make_float4(rev[0], rev[1], rev[2], rev[3]);
        *(float4*)&Im_out[idx] = make_float4(imv[0], imv[1], imv[2], imv[3]);
    }
    __syncthreads();
    // g_A[(j0+j)*32768 + b*256 + i0 + i] = A[b][i][j]
#pragma unroll
    for (int r = 0; r < 4; r++) {
        const int j = tr + r * 16;
        const int i4 = t16 * 4;
        float4 v = make_float4(sA[i4][j], sA[i4 + 1][j], sA[i4 + 2][j], sA[i4 + 3][j]);
        *(float4*)&g_A[(size_t)(j0 + j) * 32768 + b * 256 + i0 + i4] = v;
    }
}

// ============================================================================
// Kernel 4: per-k fused GEMMs via mma.sync tf32, all-cp.async 3-stage pipeline.
// Grid (4 vq, 256 k). 256 threads, warps 4(M)x2(N), warp tile 32x32.
// 24 chunks of K=32:  c 0-7:  A @ [U_o | W_z] -> acc_o, acc_z
//                     c 8-15: x @ W_o         -> acc_o
//                     c16-23: z_prev @ V_o    -> acc_o
// Epilogue: z[b,v] += hsig(acc_o+b_o) * tanh(acc_z+b_z).
// ============================================================================
#define LDA_B 144                    // 32 fp32 + 4-word pad (36 words)
#define LDB_B 288                    // 64 fp32 + 8-word pad (72 words)
#define A_BYTES (128 * LDA_B)        // 18432
#define B_BYTES (32 * LDB_B)         // 9216
#define STAGE (A_BYTES + 2 * B_BYTES)    // 36864
#define SMEM_TOT (3 * STAGE)             // 110592

__global__ __launch_bounds__(256, 2) void k_freq_mma(
    const float* __restrict__ freq_k, const float* __restrict__ freq_ki,
    const float* __restrict__ freqb, float* __restrict__ z_out)
{
    extern __shared__ char smem[];
    const uint32_t sbase = smem_u32(smem);
    const int tid = threadIdx.x, l = tid & 31, w = tid >> 5;
    const int wm = w & 3, wn = w >> 2;
    const int k = blockIdx.y, v0 = blockIdx.x * 64;

    float acc_o[2][4][4], acc_z[2][4][4];
#pragma unroll
    for (int i = 0; i < 32; i++) { ((float*)acc_o)[i] = 0.f; ((float*)acc_z)[i] = 0.f; }

    auto issue = [&](int c) {
        const uint32_t sb = sbase + (c % 3) * STAGE;
        const float* lhs;
        if (c < 8)       lhs = g_A + (size_t)k * 32768 + c * 32;
        else if (c < 16) lhs = g_xr + (c - 8) * 32;
        else             lhs = g_zr + (c - 16) * 32;
#pragma unroll
        for (int i = 0; i < 4; i++) {
            const int idx = tid + i * 256;
            const int row = idx >> 3, gq = idx & 7;
            cpa16(sb + row * LDA_B + gq * 16, lhs + row * 256 + gq * 4);
        }
        const float* b0; int strd;
        if (c < 8)       { b0 = freq_k  + (size_t)k * 196608 + (size_t)(c * 32) * 768 + v0; strd = 768; }
        else if (c < 16) { b0 = freq_ki + (size_t)k * 65536  + (size_t)((c - 8) * 32) * 256 + v0; strd = 256; }
        else             { b0 = freq_k  + (size_t)k * 196608 + (size_t)((c - 16) * 32) * 768 + 256 + v0; strd = 768; }
#pragma unroll
        for (int i = 0; i < 2; i++) {
            const int idx = tid + i * 256;
            const int row = idx >> 4, gq = idx & 15;
            cpa16(sb + A_BYTES + row * LDB_B + gq * 16, b0 + (size_t)row * strd + gq * 4);
        }
        if (c < 8) {
            const float* b1 = freq_k + (size_t)k * 196608 + (size_t)(c * 32) * 768 + 512 + v0;
#pragma unroll
            for (int i = 0; i < 2; i++) {
                const int idx = tid + i * 256;
                const int row = idx >> 4, gq = idx & 15;
                cpa16(sb + A_BYTES + B_BYTES + row * LDB_B + gq * 16, b1 + (size_t)row * 768 + gq * 4);
            }
        }
        cpa_commit();
    };

    issue(0);
    issue(1);

#pragma unroll 1
    for (int c = 0; c < 24; c++) {
        if (c < 22) cpa_wait1(); else cpa_wait0();
        __syncthreads();
        if (c + 2 < 24) issue(c + 2);

        const uint32_t sAc = sbase + (c % 3) * STAGE;
        const uint32_t sB0 = sAc + A_BYTES;
        const uint32_t sB1 = sB0 + B_BYTES;
        const bool dual = (c < 8);

#pragma unroll
        for (int s = 0; s < 4; s++) {
            uint32_t a[2][4];
            const uint32_t abase = sAc + (uint32_t)(((wm * 32 + (l >> 2)) * 36 + s * 8 + (l & 3)) * 4);
#pragma unroll
            for (int mt = 0; mt < 2; mt++) {
                const uint32_t ab = abase + mt * (16 * LDA_B);
                a[mt][0] = __float_as_uint(lds32(ab));
                a[mt][1] = __float_as_uint(lds32(ab + 8 * LDA_B));
                a[mt][2] = __float_as_uint(lds32(ab + 16));
                a[mt][3] = __float_as_uint(lds32(ab + 8 * LDA_B + 16));
            }
            const uint32_t bbase = (uint32_t)(((s * 8 + (l & 3)) * 72 + wn * 32 + (l >> 2)) * 4);
#pragma unroll
            for (int nt = 0; nt < 4; nt++) {
                const uint32_t b0r = lds_rna(sB0 + bbase + nt * 32);
                const uint32_t b1r = lds_rna(sB0 + bbase + 4 * LDB_B + nt * 32);
#pragma unroll
                for (int mt = 0; mt < 2; mt++)
                    mma_tf32(acc_o[mt][nt], a[mt], b0r, b1r);
            }
            if (dual) {
#pragma unroll
                for (int nt = 0; nt < 4; nt++) {
                    const uint32_t b0r = lds_rna(sB1 + bbase + nt * 32);
                    const uint32_t b1r = lds_rna(sB1 + bbase + 4 * LDB_B + nt * 32);
#pragma unroll
                    for (int mt = 0; mt < 2; mt++)
                        mma_tf32(acc_z[mt][nt], a[mt], b0r, b1r);
                }
            }
        }
    }

    // ---- epilogue: z[b,v] += hsig(C_o + b_o) * tanh(C_z + b_z) --------------
    const float* bo = freqb + (size_t)k * 256;
    const float* bz = freqb + (size_t)(256 + k) * 256;
#pragma unroll
    for (int mt = 0; mt < 2; mt++)
#pragma unroll
        for (int nt = 0; nt < 4; nt++)
#pragma unroll
            for (int r = 0; r < 4; r++) {
                const int b = wm * 32 + mt * 16 + (l >> 2) + (r >> 1) * 8;
                const int v = v0 + wn * 32 + nt * 8 + (l & 3) * 2 + (r & 1);
                const float o = hsig(acc_o[mt][nt][r] + __ldg(bo + v));
                const float zz = o * tanhf(acc_z[mt][nt][r] + __ldg(bz + v));
                atomicAdd(&z_out[b * 256 + v], zz);
            }
}

// ============================================================================
// launch
// ============================================================================
extern "C" void kernel_launch(void* const* d_in, const int* in_sizes, int n_in,
                              void* d_out, int out_size)
{
    const float* x        = (const float*)d_in[0];
    const float* t        = (const float*)d_in[1];
    const float* z_prev   = (const float*)d_in[2];
    const float* Im_prev  = (const float*)d_in[3];
    const float* Re_prev  = (const float*)d_in[4];
    const float* omg_prev = (const float*)d_in[5];
    const float* kern     = (const float*)d_in[6];
    const float* recur    = (const float*)d_in[7];
    const float* freq_k   = (const float*)d_in[8];
    const float* freq_ki  = (const float*)d_in[9];
    const float* bias     = (const float*)d_in[10];
    const float* freqb    = (const float*)d_in[11];

    float* out     = (float*)d_out;
    float* z_out   = out;
    float* im_out  = out + 32768;
    float* re_out  = out + 32768 + 8388608;
    float* omg_out = out + 32768 + 2 * 8388608;

    static int smem_set = 0;
    if (!smem_set) {
        cudaFuncSetAttribute(k_freq_mma, cudaFuncAttributeMaxDynamicSharedMemorySize, SMEM_TOT);
        smem_set = 1;
    }

    cudaMemsetAsync(z_out, 0, 32768 * sizeof(float), 0);
    k_gates_gemm<<<dim3(20, 4), 256>>>(x, z_prev, kern, recur, bias);
    k_gates_ew<<<128, 256>>>(x, z_prev, omg_prev, t, omg_out);
    k_reim<<<dim3(4, 4, 128), 256>>>(Re_prev, Im_prev, im_out, re_out);
    k_freq_mma<<<dim3(4, 256), 256, SMEM_TOT>>>(freq_k, freq_ki, freqb, z_out);
}

// round 9
// speedup vs baseline: 1.3294x; 1.3294x over previous
#include <cuda_runtime.h>
#include <cuda_fp16.h>
#include <math.h>
#include <stdint.h>

#define Bq 128
#define Uq 256
#define NG 1280

// ---------------- scratch (static device globals) ----------------------------
__device__ float g_gsum[Bq * NG];
__device__ float g_c  [Bq * Uq];
__device__ float g_fre[Bq * Uq];
__device__ float g_ste[Bq * Uq];
__device__ float g_cos[Bq * Uq];
__device__ float g_sin[Bq * Uq];
__device__ __half g_Ah[(size_t)Uq * Bq * Uq];  // [k][b][u], 16.8MB
__device__ __half g_xh[Bq * Uq];
__device__ __half g_zh[Bq * Uq];

__device__ __forceinline__ float hsig(float v) {
    return fminf(fmaxf(0.2f * v + 0.5f, 0.0f), 1.0f);
}

// ---------------- PTX helpers (sm_80-level only) ------------------------------
__device__ __forceinline__ uint32_t smem_u32(const void* p) {
    uint32_t a;
    asm("{ .reg .u64 t; cvta.to.shared.u64 t, %1; cvt.u32.u64 %0, t; }" : "=r"(a) : "l"(p));
    return a;
}
__device__ __forceinline__ uint32_t packh(float lo, float hi) {
    __half2 h = __floats2half2_rn(lo, hi);
    return *(uint32_t*)&h;
}
__device__ __forceinline__ void sts128(uint32_t a, uint32_t r0, uint32_t r1, uint32_t r2, uint32_t r3) {
    asm volatile("st.shared.v4.b32 [%0], {%1,%2,%3,%4};"
                 :: "r"(a), "r"(r0), "r"(r1), "r"(r2), "r"(r3) : "memory");
}
__device__ __forceinline__ void cpa16(uint32_t dst, const void* src) {
    asm volatile("cp.async.cg.shared.global [%0], [%1], 16;" :: "r"(dst), "l"(src) : "memory");
}
__device__ __forceinline__ void cpa_commit() {
    asm volatile("cp.async.commit_group;" ::: "memory");
}
__device__ __forceinline__ void cpa_wait0() {
    asm volatile("cp.async.wait_group 0;" ::: "memory");
}
__device__ __forceinline__ void ldsm4(uint32_t* r, uint32_t addr) {
    asm volatile("ldmatrix.sync.aligned.m8n8.x4.shared.b16 {%0,%1,%2,%3}, [%4];"
                 : "=r"(r[0]), "=r"(r[1]), "=r"(r[2]), "=r"(r[3]) : "r"(addr));
}
__device__ __forceinline__ void ldsm4t(uint32_t* r, uint32_t addr) {
    asm volatile("ldmatrix.sync.aligned.m8n8.x4.trans.shared.b16 {%0,%1,%2,%3}, [%4];"
                 : "=r"(r[0]), "=r"(r[1]), "=r"(r[2]), "=r"(r[3]) : "r"(addr));
}
__device__ __forceinline__ void mma_f16(float* c, const uint32_t* a, const uint32_t* b) {
    asm volatile(
        "mma.sync.aligned.m16n8k16.row.col.f32.f16.f16.f32 "
        "{%0,%1,%2,%3}, {%4,%5,%6,%7}, {%8,%9}, {%0,%1,%2,%3};"
        : "+f"(c[0]), "+f"(c[1]), "+f"(c[2]), "+f"(c[3])
        : "r"(a[0]), "r"(a[1]), "r"(a[2]), "r"(a[3]), "r"(b[0]), "r"(b[1]));
}

// ============================================================================
// Kernel 1: g_gsum = x @ kernel + z_prev @ recur_k + bias.  32x64 tiles.
// Grid (20 j, 4 b), 256 threads, 2x4 per-thread tile.
// ============================================================================
__global__ __launch_bounds__(256) void k_gates_gemm(
    const float* __restrict__ x, const float* __restrict__ z_prev,
    const float* __restrict__ kern, const float* __restrict__ recur,
    const float* __restrict__ bias)
{
    __shared__ float sX[32][33];   // [ku][b], transposed
    __shared__ float sW[32][68];
    const int tid = threadIdx.x;
    const int j0 = blockIdx.x * 64, b0 = blockIdx.y * 32;
    const int rg = tid >> 4, cg = tid & 15;
    float acc[2][4];
#pragma unroll
    for (int i = 0; i < 2; i++)
#pragma unroll
        for (int j = 0; j < 4; j++) acc[i][j] = 0.f;

#pragma unroll
    for (int pass = 0; pass < 2; pass++) {
        const float* L = pass ? z_prev : x;
        const float* W = pass ? recur : kern;
        for (int d0 = 0; d0 < 256; d0 += 32) {
            {
                const int lb = tid >> 3, lu = (tid & 7) * 4;
                float4 v = *(const float4*)&L[(b0 + lb) * 256 + d0 + lu];
                sX[lu][lb] = v.x; sX[lu + 1][lb] = v.y;
                sX[lu + 2][lb] = v.z; sX[lu + 3][lb] = v.w;
            }
#pragma unroll
            for (int i2 = 0; i2 < 2; i2++) {
                const int wu = (tid >> 4) + i2 * 16, wc = (tid & 15) * 4;
                *(float4*)&sW[wu][wc] = *(const float4*)&W[(d0 + wu) * NG + j0 + wc];
            }
            __syncthreads();
#pragma unroll
            for (int kk = 0; kk < 32; kk++) {
                float a0 = sX[kk][rg * 2], a1 = sX[kk][rg * 2 + 1];
                float bb[4];
#pragma unroll
                for (int j = 0; j < 4; j++) bb[j] = sW[kk][cg * 4 + j];
#pragma unroll
                for (int j = 0; j < 4; j++) { acc[0][j] += a0 * bb[j]; acc[1][j] += a1 * bb[j]; }
            }
            __syncthreads();
        }
    }
#pragma unroll
    for (int i = 0; i < 2; i++) {
        const int b = b0 + rg * 2 + i;
#pragma unroll
        for (int j = 0; j < 4; j++) {
            const int jj = j0 + cg * 4 + j;
            g_gsum[b * NG + jj] = acc[i][j] + bias[jj];
        }
    }
}

// ============================================================================
// Kernel 2: elementwise gates + omega out + cos/sin + fp16 copies of x, z_prev
// ============================================================================
__global__ __launch_bounds__(256) void k_gates_ew(
    const float* __restrict__ x, const float* __restrict__ z_prev,
    const float* __restrict__ omg_prev, const float* __restrict__ t,
    float* __restrict__ out_omg)
{
    const int idx = blockIdx.x * blockDim.x + threadIdx.x;
    const int b = idx >> 8, u = idx & 255;
    const float* g = &g_gsum[b * NG];
    const float i_g = hsig(g[u]);
    const float fre = hsig(g[Uq + u]);
    const float ste = hsig(g[2 * Uq + u]);
    const float gg  = tanhf(g[3 * Uq + u]);
    g_c[idx] = i_g * gg; g_fre[idx] = fre; g_ste[idx] = ste;
    const float th = omg_prev[idx] * t[b];
    g_cos[idx] = cosf(th); g_sin[idx] = sinf(th);
    out_omg[idx] = g[4 * Uq + u];
    g_xh[idx] = __float2half_rn(x[idx]);
    g_zh[idx] = __float2half_rn(z_prev[idx]);
}

// ============================================================================
// Kernel 3: Re/Im update + A = sqrt(Re^2+Im^2) -> g_Ah [k][b][u] (fp16)
// float4 I/O on the big streams. Block: one b, 64(i=u) x 64(j=k) tile.
// ============================================================================
__global__ __launch_bounds__(256) void k_reim(
    const float* __restrict__ Re_prev, const float* __restrict__ Im_prev,
    float* __restrict__ Im_out, float* __restrict__ Re_out)
{
    __shared__ float sA[64][65];
    const int b = blockIdx.z, i0 = blockIdx.y * 64, j0 = blockIdx.x * 64;
    const int t16 = threadIdx.x & 15, tr = threadIdx.x >> 4;
    const int j4 = t16 * 4;

    const float4 fre4 = *(const float4*)&g_fre[b * Uq + j0 + j4];
    const float4 cos4 = *(const float4*)&g_cos[b * Uq + j0 + j4];
    const float4 sin4 = *(const float4*)&g_sin[b * Uq + j0 + j4];
    const float frev[4] = {fre4.x, fre4.y, fre4.z, fre4.w};
    const float cosv[4] = {cos4.x, cos4.y, cos4.z, cos4.w};
    const float sinv[4] = {sin4.x, sin4.y, sin4.z, sin4.w};

#pragma unroll
    for (int r = 0; r < 4; r++) {
        const int i = tr + r * 16;
        const float ste_i = g_ste[b * Uq + i0 + i];
        const float ci    = g_c  [b * Uq + i0 + i];
        const size_t idx = ((size_t)b * Uq + (i0 + i)) * Uq + j0 + j4;
        const float4 rp = *(const float4*)&Re_prev[idx];
        const float4 ip = *(const float4*)&Im_prev[idx];
        const float rpv[4] = {rp.x, rp.y, rp.z, rp.w};
        const float ipv[4] = {ip.x, ip.y, ip.z, ip.w};
        float rev[4], imv[4];
#pragma unroll
        for (int q = 0; q < 4; q++) {
            const float f = ste_i * frev[q];
            rev[q] = f * rpv[q] + ci * cosv[q];
            imv[q] = f * ipv[q] + ci * sinv[q];
            sA[i][j4 + q] = sqrtf(rev[q] * rev[q] + imv[q] * imv[q]);
        }
        *(float4*)&Re_out[idx] = make_float4(rev[0], rev[1], rev[2], rev[3]);
        *(float4*)&Im_out[idx] = make_float4(imv[0], imv[1], imv[2], imv[3]);
    }
    __syncthreads();
    // g_Ah[((j0+j)*128 + b)*256 + i0 + i] = A[b][i][j]; write 4 i's as 2x half2
#pragma unroll
    for (int r = 0; r < 4; r++) {
        const int j = tr + r * 16;
        const int i4 = t16 * 4;
        __half2 h0 = __floats2half2_rn(sA[i4][j],     sA[i4 + 1][j]);
        __half2 h1 = __floats2half2_rn(sA[i4 + 2][j], sA[i4 + 3][j]);
        uint2 v = make_uint2(*(uint32_t*)&h0, *(uint32_t*)&h1);
        *(uint2*)&g_Ah[((size_t)(j0 + j) * 128 + b) * 256 + i0 + i4] = v;
    }
}

// ============================================================================
// Kernel 4: per-k fused GEMMs via mma.sync fp16 (Round-7 mainloop).
// Grid (4 vq, 256 k) -- vq fastest so same-k blocks share A via L2.
// 256 threads, warps 4(M)x2(N), warp tile 32x32. Block tile 128(b) x 64(v).
// Chunks of K=64:  c 0-3:  A @ [U_o | W_z]  -> acc_o, acc_z  (A read once)
//                  c 4-7:  x @ W_o          -> acc_o
//                  c 8-11: z_prev @ V_o     -> acc_o
// Epilogue: z[b,v] += hsig(acc_o+b_o) * tanh(acc_z+b_z) via atomics.
// ============================================================================
#define LDA 144                 // 64 fp16 (128B) + 16B pad
#define LDB 144
#define A_BYTES (128*LDA)       // 18432
#define B_BYTES (64*LDB)        // 9216
#define STG (A_BYTES + 2*B_BYTES)   // 36864
#define SMEM_TOT (2*STG)            // 73728

__global__ __launch_bounds__(256, 2) void k_freq_mma(
    const float* __restrict__ freq_k, const float* __restrict__ freq_ki,
    const float* __restrict__ freqb, float* __restrict__ z_out)
{
    extern __shared__ char smem[];
    const uint32_t sbase = smem_u32(smem);
    const int tid = threadIdx.x, l = tid & 31, w = tid >> 5;
    const int wm = w & 3, wn = w >> 2;
    const int k = blockIdx.y, v0 = blockIdx.x * 64;

    float acc_o[2][4][4], acc_z[2][4][4];
#pragma unroll
    for (int i = 0; i < 32; i++) { ((float*)acc_o)[i] = 0.f; ((float*)acc_z)[i] = 0.f; }

    const uint32_t a_base = (uint32_t)((wm * 32 + (l & 15)) * LDA + (l >> 4) * 16);
    const uint32_t b_base = (uint32_t)((l & 15) * LDB + wn * 64 + (l >> 4) * 16);

    auto lhs_of = [&](int c) -> const __half* {
        if (c < 4)  return g_Ah + (size_t)k * 32768 + c * 64;
        if (c < 8)  return g_xh + (c - 4) * 64;
        return g_zh + (c - 8) * 64;
    };
    auto b0_of = [&](int c, int& stride) -> const float* {
        if (c < 4)  { stride = 768; return freq_k  + (size_t)k * 196608 + (size_t)c * 64 * 768 + v0; }
        if (c < 8)  { stride = 256; return freq_ki + (size_t)k * 65536  + (size_t)(c - 4) * 64 * 256 + v0; }
        stride = 768; return freq_k + (size_t)k * 196608 + (size_t)(c - 8) * 64 * 768 + 256 + v0;
    };

    float4 hb[8];

    auto load_lhs = [&](int c, int buf) {
        const __half* ls = lhs_of(c);
        const uint32_t dst = sbase + buf * STG;
#pragma unroll
        for (int i = 0; i < 4; i++) {
            const int idx = tid + i * 256;
            const int row = idx >> 3, g = idx & 7;
            cpa16(dst + row * LDA + g * 16, ls + row * 256 + g * 8);
        }
        cpa_commit();
    };
    auto load_b_regs = [&](int c) {
        int st; const float* b0 = b0_of(c, st);
#pragma unroll
        for (int i = 0; i < 2; i++) {
            const int idx = tid + i * 256;
            const int r = idx >> 3, g = idx & 7;
            hb[2 * i]     = __ldg((const float4*)(b0 + (size_t)r * st + g * 8));
            hb[2 * i + 1] = __ldg((const float4*)(b0 + (size_t)r * st + g * 8 + 4));
        }
        if (c < 4) {
            const float* b1 = freq_k + (size_t)k * 196608 + (size_t)c * 64 * 768 + 512 + v0;
#pragma unroll
            for (int i = 0; i < 2; i++) {
                const int idx = tid + i * 256;
                const int r = idx >> 3, g = idx & 7;
                hb[4 + 2 * i]     = __ldg((const float4*)(b1 + (size_t)r * 768 + g * 8));
                hb[4 + 2 * i + 1] = __ldg((const float4*)(b1 + (size_t)r * 768 + g * 8 + 4));
            }
        }
    };
    auto store_b = [&](int c, int buf) {
        const uint32_t sB0 = sbase + buf * STG + A_BYTES;
#pragma unroll
        for (int i = 0; i < 2; i++) {
            const int idx = tid + i * 256;
            const int r = idx >> 3, g = idx & 7;
            sts128(sB0 + r * LDB + g * 16,
                   packh(hb[2 * i].x, hb[2 * i].y), packh(hb[2 * i].z, hb[2 * i].w),
                   packh(hb[2 * i + 1].x, hb[2 * i + 1].y), packh(hb[2 * i + 1].z, hb[2 * i + 1].w));
        }
        if (c < 4) {
            const uint32_t sB1 = sB0 + B_BYTES;
#pragma unroll
            for (int i = 0; i < 2; i++) {
                const int idx = tid + i * 256;
                const int r = idx >> 3, g = idx & 7;
                sts128(sB1 + r * LDB + g * 16,
                       packh(hb[4 + 2 * i].x, hb[4 + 2 * i].y), packh(hb[4 + 2 * i].z, hb[4 + 2 * i].w),
                       packh(hb[5 + 2 * i].x, hb[5 + 2 * i].y), packh(hb[5 + 2 * i].z, hb[5 + 2 * i].w));
            }
        }
    };

    // ---- prologue ----------------------------------------------------------
    load_lhs(0, 0);
    load_b_regs(0);

#pragma unroll 1
    for (int c = 0; c < 12; c++) {
        const int buf = c & 1;
        store_b(c, buf);
        cpa_wait0();
        __syncthreads();

        if (c < 11) {
            load_lhs(c + 1, buf ^ 1);
            load_b_regs(c + 1);
        }

        const uint32_t sA  = sbase + buf * STG;
        const uint32_t sB0 = sA + A_BYTES;
        const uint32_t sB1 = sB0 + B_BYTES;

#pragma unroll
        for (int s = 0; s < 4; s++) {
            uint32_t af[2][4], bf[2][4];
            ldsm4(af[0], sA + a_base + s * 32);
            ldsm4(af[1], sA + a_base + 16 * LDA + s * 32);
#pragma unroll
            for (int nt = 0; nt < 2; nt++)
                ldsm4t(bf[nt], sB0 + b_base + s * 16 * LDB + nt * 32);
#pragma unroll
            for (int mt = 0; mt < 2; mt++)
#pragma unroll
                for (int nt = 0; nt < 2; nt++) {
                    mma_f16(acc_o[mt][2 * nt],     af[mt], &bf[nt][0]);
                    mma_f16(acc_o[mt][2 * nt + 1], af[mt], &bf[nt][2]);
                }
            if (c < 4) {
                uint32_t bz[2][4];
#pragma unroll
                for (int nt = 0; nt < 2; nt++)
                    ldsm4t(bz[nt], sB1 + b_base + s * 16 * LDB + nt * 32);
#pragma unroll
                for (int mt = 0; mt < 2; mt++)
#pragma unroll
                    for (int nt = 0; nt < 2; nt++) {
                        mma_f16(acc_z[mt][2 * nt],     af[mt], &bz[nt][0]);
                        mma_f16(acc_z[mt][2 * nt + 1], af[mt], &bz[nt][2]);
                    }
            }
        }
    }

    // ---- epilogue: zz = hsig(C_o + b_o) * tanh(C_z + b_z); z += zz ----------
    const float* bo = freqb + (size_t)k * 256;
    const float* bz = freqb + (size_t)(256 + k) * 256;
#pragma unroll
    for (int mt = 0; mt < 2; mt++)
#pragma unroll
        for (int j = 0; j < 4; j++)
#pragma unroll
            for (int r = 0; r < 4; r++) {
                const int b = wm * 32 + mt * 16 + (l >> 2) + (r >> 1) * 8;
                const int v = v0 + wn * 32 + j * 8 + (l & 3) * 2 + (r & 1);
                const float o = hsig(acc_o[mt][j][r] + __ldg(bo + v));
                const float zz = o * tanhf(acc_z[mt][j][r] + __ldg(bz + v));
                atomicAdd(&z_out[b * 256 + v], zz);
            }
}

// ============================================================================
// launch
// ============================================================================
extern "C" void kernel_launch(void* const* d_in, const int* in_sizes, int n_in,
                              void* d_out, int out_size)
{
    const float* x        = (const float*)d_in[0];
    const float* t        = (const float*)d_in[1];
    const float* z_prev   = (const float*)d_in[2];
    const float* Im_prev  = (const float*)d_in[3];
    const float* Re_prev  = (const float*)d_in[4];
    const float* omg_prev = (const float*)d_in[5];
    const float* kern     = (const float*)d_in[6];
    const float* recur    = (const float*)d_in[7];
    const float* freq_k   = (const float*)d_in[8];
    const float* freq_ki  = (const float*)d_in[9];
    const float* bias     = (const float*)d_in[10];
    const float* freqb    = (const float*)d_in[11];

    float* out     = (float*)d_out;
    float* z_out   = out;
    float* im_out  = out + 32768;
    float* re_out  = out + 32768 + 8388608;
    float* omg_out = out + 32768 + 2 * 8388608;

    static int smem_set = 0;
    if (!smem_set) {
        cudaFuncSetAttribute(k_freq_mma, cudaFuncAttributeMaxDynamicSharedMemorySize, SMEM_TOT);
        smem_set = 1;
    }

    cudaMemsetAsync(z_out, 0, 32768 * sizeof(float), 0);
    k_gates_gemm<<<dim3(20, 4), 256>>>(x, z_prev, kern, recur, bias);
    k_gates_ew<<<128, 256>>>(x, z_prev, omg_prev, t, omg_out);
    k_reim<<<dim3(4, 4, 128), 256>>>(Re_prev, Im_prev, im_out, re_out);
    k_freq_mma<<<dim3(4, 256), 256, SMEM_TOT>>>(freq_k, freq_ki, freqb, z_out);
}